// round 12
// baseline (speedup 1.0000x reference)
#include <cuda_runtime.h>
#include <cuda_fp16.h>
#include <cstdint>

// N=100000, E=1600000, D=8, K=1, C=32 (dims from in_sizes at runtime).
#define MAXN 100352
#define MAXE 1638400
#define SCAN_BLK 1024
#define MAX_SB 128   // max scan blocks (ceil(MAXN/1024) = 98)

__device__ __align__(16) __half g_xgh[MAXN * 32];    // x @ g (fp16 gather payload)
__device__ __align__(16) float g_rootb[MAXN * 32];   // root term (layer 1)
__device__ __align__(16) float g_rootb2[MAXN * 32];  // root term (layer 2)
__device__ __align__(16) float g_h[MAXN * 32];       // layer-1 output (fp32)
__device__ __align__(16) uint2 g_edges[MAXE];        // (src, half2(gau1,gau2)) sorted by dst
__device__ int g_cnt[MAXN];                           // in-degree histogram
__device__ int g_rowptr[MAXN + 1];                    // CSR row pointers (by dst)
__device__ int g_cursor[MAXN];                        // scatter cursors
__device__ int g_bsum[MAX_SB];                        // scan block sums
__device__ __align__(16) float g_prm[32];             // [0:8) inv1, [8:16) inv2, [16:24) mu1, [24:32) mu2

// ---------------- tiny prep: hoist sigma reciprocals ----------------
// inv[d] = -0.5 / (eps + sigma[d]^2)   (16 full-precision divides, once/call)
__global__ void prep_k(const float* __restrict__ s1, const float* __restrict__ s2,
                       const float* __restrict__ mu1, const float* __restrict__ mu2,
                       float* __restrict__ prm) {
    int t = threadIdx.x;
    if (t < 8) {
        float s = s1[t];
        prm[t] = -0.5f / (1e-15f + s * s);
        prm[16 + t] = mu1[t];
    } else if (t < 16) {
        float s = s2[t - 8];
        prm[t] = -0.5f / (1e-15f + s * s);
        prm[16 + t] = mu2[t - 8];
    }
}

// ---------------- CSR build ----------------

__global__ void __launch_bounds__(256) hist_k(const int* __restrict__ ei, int* __restrict__ cnt, int E) {
    int e = blockIdx.x * blockDim.x + threadIdx.x;
    if (e < E) atomicAdd(cnt + __ldg(ei + E + e), 1);
}

// Per-block exclusive scan of 1024 counts; block totals to bsum.
__global__ void __launch_bounds__(SCAN_BLK) scan1_k(const int* __restrict__ cnt,
                                                    int* __restrict__ rowptr,
                                                    int* __restrict__ bsum, int N) {
    __shared__ int sh[SCAN_BLK];
    int t = threadIdx.x;
    int i = blockIdx.x * SCAN_BLK + t;
    int v = (i < N) ? cnt[i] : 0;
    sh[t] = v;
    __syncthreads();
    for (int off = 1; off < SCAN_BLK; off <<= 1) {
        int add = (t >= off) ? sh[t - off] : 0;
        __syncthreads();
        sh[t] += add;
        __syncthreads();
    }
    if (i < N) rowptr[i] = sh[t] - v;  // exclusive
    if (t == SCAN_BLK - 1) bsum[blockIdx.x] = sh[t];
}

// Fused scan2+scan3: each block computes its own block-offset (warp-reduced
// prefix over <=98 block sums), then applies it and initializes cursors.
__global__ void __launch_bounds__(SCAN_BLK) scan23_k(int* __restrict__ rowptr,
                                                     int* __restrict__ cursor,
                                                     const int* __restrict__ bsum,
                                                     int N, int E) {
    __shared__ int s_off;
    int t = threadIdx.x;
    if (t < 32) {
        int acc = 0;
        for (int j = t; j < blockIdx.x; j += 32) acc += __ldg(bsum + j);
        acc += __shfl_xor_sync(0xffffffffu, acc, 16);
        acc += __shfl_xor_sync(0xffffffffu, acc, 8);
        acc += __shfl_xor_sync(0xffffffffu, acc, 4);
        acc += __shfl_xor_sync(0xffffffffu, acc, 2);
        acc += __shfl_xor_sync(0xffffffffu, acc, 1);
        if (t == 0) s_off = acc;
    }
    __syncthreads();
    int i = blockIdx.x * SCAN_BLK + t;
    if (i < N) {
        int v = rowptr[i] + s_off;
        rowptr[i] = v;
        cursor[i] = v;
    }
    if (i == 0) rowptr[N] = E;
}

// Gaussian weights (both layers, packed half2) + scatter 8B records to the
// dst-sorted slot. Pure-FMA inner loop (reciprocals hoisted into g_prm).
__global__ void __launch_bounds__(256) gau_scatter_k(
    const int* __restrict__ ei,
    const float4* __restrict__ ea,    // [E,8] viewed as [E,2] float4
    const float* __restrict__ prm,    // [0:8) inv1, [8:16) inv2, [16:24) mu1, [24:32) mu2
    int* __restrict__ cursor,
    uint2* __restrict__ edges, int E) {
    int e = blockIdx.x * blockDim.x + threadIdx.x;
    if (e >= E) return;
    float4 a = ea[e * 2];
    float4 b = ea[e * 2 + 1];
    float v[8] = {a.x, a.y, a.z, a.w, b.x, b.y, b.z, b.w};
    float t1 = 0.f, t2 = 0.f;
#pragma unroll
    for (int d = 0; d < 8; d++) {
        float d1 = v[d] - __ldg(prm + 16 + d);
        float d2 = v[d] - __ldg(prm + 24 + d);
        t1 = fmaf(d1 * d1, __ldg(prm + d), t1);
        t2 = fmaf(d2 * d2, __ldg(prm + 8 + d), t2);
    }
    int src = __ldg(ei + e);
    int dst = __ldg(ei + E + e);
    int pos = atomicAdd(cursor + dst, 1);
    __half2 gp = __floats2half2_rn(__expf(t1), __expf(t2));
    uint2 rec;
    rec.x = (unsigned)src;
    rec.y = *reinterpret_cast<unsigned*>(&gp);
    edges[pos] = rec;
}

// ---------------- GEMM (register weights, fp16 xg output) ----------------

__global__ void __launch_bounds__(256) gemm_k(
    const float* __restrict__ xin,
    const float* __restrict__ g,
    const float* __restrict__ root,
    const float* __restrict__ bias,
    __half* __restrict__ xg,
    float* __restrict__ rb_out,
    int N) {
    __shared__ float sx[128][32];
    const int t = threadIdx.x;
    const int lane = t & 31;
    const int w = t >> 5;

    float wg[32], wr[32];
#pragma unroll
    for (int k = 0; k < 32; k++) {
        wg[k] = __ldg(g + k * 32 + lane);
        wr[k] = __ldg(root + k * 32 + lane);
    }
    const float bv = __ldg(bias + lane);

    const int base = blockIdx.x * 128;
    const int nrows = min(128, N - base);

    for (int i = t; i < nrows * 32; i += 256)
        sx[i >> 5][i & 31] = xin[(size_t)base * 32 + i];
    __syncthreads();

    for (int r = w; r < nrows; r += 8) {
        float a = 0.0f, b = bv;
#pragma unroll
        for (int k = 0; k < 32; k++) {
            float xv = sx[r][k];
            a = fmaf(xv, wg[k], a);
            b = fmaf(xv, wr[k], b);
        }
        size_t o = (size_t)(base + r) * 32 + lane;
        xg[o] = __float2half_rn(a);
        rb_out[o] = b;
    }
}

// ---------------- Pull aggregation: 2 edges per warp-instruction ----------------
// One warp per dst node. Lanes 0-15 process edge A, lanes 16-31 edge B; each
// lane owns 2 channels as one __half2 (4B load). Records loaded coalesced,
// redistributed via shfl; epilogue folds half-warps with shfl_xor(16).
template <int LAYER>
__global__ void __launch_bounds__(256) pull_k(
    const int* __restrict__ rowptr,
    const uint2* __restrict__ edges,
    const __half2* __restrict__ xg,   // [N,16] half2 rows
    const float2* __restrict__ rootb, // [N,16] float2 rows
    float2* __restrict__ out,         // [N,16] float2 rows
    int N) {
    int warp = (blockIdx.x * blockDim.x + threadIdx.x) >> 5;
    int lane = threadIdx.x & 31;
    if (warp >= N) return;

    const int c2 = lane & 15;     // channel-pair index (channels 2*c2, 2*c2+1)
    const int which = lane >> 4;  // 0 -> even edge, 1 -> odd edge

    int s = __ldg(rowptr + warp);
    int e = __ldg(rowptr + warp + 1);
    int deg = e - s;

    float ax0 = 0.f, ay0 = 0.f, ax1 = 0.f, ay1 = 0.f;

    for (int j = s; j < e; j += 32) {
        int m = min(32, e - j);
        // cooperative coalesced record load: lane i -> record j+i
        int   si = 0;
        float gv = 0.f;
        if (lane < m) {
            uint2 r = edges[j + lane];
            si = (int)r.x;
            __half2 gp = *reinterpret_cast<__half2*>(&r.y);
            gv = (LAYER == 1) ? __low2float(gp) : __high2float(gp);
        }
        int k = 0;
        for (; k + 4 <= m; k += 4) {
            int   sa = __shfl_sync(0xffffffffu, si, k + which);
            float ga = __shfl_sync(0xffffffffu, gv, k + which);
            int   sb = __shfl_sync(0xffffffffu, si, k + 2 + which);
            float gb = __shfl_sync(0xffffffffu, gv, k + 2 + which);
            float2 xa = __half22float2(__ldg(xg + (size_t)sa * 16 + c2));
            float2 xb = __half22float2(__ldg(xg + (size_t)sb * 16 + c2));
            ax0 = fmaf(ga, xa.x, ax0);
            ay0 = fmaf(ga, xa.y, ay0);
            ax1 = fmaf(gb, xb.x, ax1);
            ay1 = fmaf(gb, xb.y, ay1);
        }
        for (; k + 2 <= m; k += 2) {
            int   sa = __shfl_sync(0xffffffffu, si, k + which);
            float ga = __shfl_sync(0xffffffffu, gv, k + which);
            float2 xa = __half22float2(__ldg(xg + (size_t)sa * 16 + c2));
            ax0 = fmaf(ga, xa.x, ax0);
            ay0 = fmaf(ga, xa.y, ay0);
        }
        if (k < m) {  // single leftover edge: only the 'which==0' half contributes
            int   sa = __shfl_sync(0xffffffffu, si, k);
            float ga = __shfl_sync(0xffffffffu, gv, k);
            if (which == 0) {
                float2 xa = __half22float2(__ldg(xg + (size_t)sa * 16 + c2));
                ax0 = fmaf(ga, xa.x, ax0);
                ay0 = fmaf(ga, xa.y, ay0);
            }
        }
    }

    float ax = ax0 + ax1;
    float ay = ay0 + ay1;
    ax += __shfl_xor_sync(0xffffffffu, ax, 16);
    ay += __shfl_xor_sync(0xffffffffu, ay, 16);

    if (lane < 16) {
        float rinv = (deg > 0) ? (1.0f / (float)deg) : 0.0f;
        size_t o = (size_t)warp * 16 + c2;
        float2 r = __ldg(rootb + o);
        float2 ov;
        ov.x = ax * rinv + r.x;
        ov.y = ay * rinv + r.y;
        out[o] = ov;
    }
}

extern "C" void kernel_launch(void* const* d_in, const int* in_sizes, int n_in,
                              void* d_out, int out_size) {
    const int*   ei  = (const int*)d_in[0];
    const float* ew  = (const float*)d_in[1];
    const float* x   = (const float*)d_in[2];
    const float* g1  = (const float*)d_in[3];
    const float* mu1 = (const float*)d_in[4];
    const float* s1  = (const float*)d_in[5];
    const float* r1  = (const float*)d_in[6];
    const float* b1  = (const float*)d_in[7];
    const float* g2  = (const float*)d_in[8];
    const float* mu2 = (const float*)d_in[9];
    const float* s2  = (const float*)d_in[10];
    const float* r2  = (const float*)d_in[11];
    const float* b2  = (const float*)d_in[12];

    const int E = in_sizes[0] / 2;
    const int N = in_sizes[2] / 32;

    __half* xgh;
    float *rootb, *rootb2, *h, *prm;
    uint2* edges;
    int *cnt, *rowptr, *cursor, *bsum;
    cudaGetSymbolAddress((void**)&xgh, g_xgh);
    cudaGetSymbolAddress((void**)&rootb, g_rootb);
    cudaGetSymbolAddress((void**)&rootb2, g_rootb2);
    cudaGetSymbolAddress((void**)&h, g_h);
    cudaGetSymbolAddress((void**)&edges, g_edges);
    cudaGetSymbolAddress((void**)&cnt, g_cnt);
    cudaGetSymbolAddress((void**)&rowptr, g_rowptr);
    cudaGetSymbolAddress((void**)&cursor, g_cursor);
    cudaGetSymbolAddress((void**)&bsum, g_bsum);
    cudaGetSymbolAddress((void**)&prm, g_prm);

    const int nb = (N + SCAN_BLK - 1) / SCAN_BLK;
    const int eb = (E + 255) / 256;
    const int gemm_blocks = (N + 127) / 128;
    const int pull_blocks = (N + 7) / 8;

    // ---- CSR build (shared by both layers) ----
    prep_k<<<1, 32>>>(s1, s2, mu1, mu2, prm);
    cudaMemsetAsync(cnt, 0, (size_t)N * sizeof(int), 0);
    hist_k<<<eb, 256>>>(ei, cnt, E);
    scan1_k<<<nb, SCAN_BLK>>>(cnt, rowptr, bsum, N);
    scan23_k<<<nb, SCAN_BLK>>>(rowptr, cursor, bsum, N, E);
    gau_scatter_k<<<eb, 256>>>(ei, (const float4*)ew, prm, cursor, edges, E);

    // ---- layer 1 ----
    gemm_k<<<gemm_blocks, 256>>>(x, g1, r1, b1, xgh, rootb, N);
    pull_k<1><<<pull_blocks, 256>>>(rowptr, edges, (const __half2*)xgh,
                                    (const float2*)rootb, (float2*)h, N);

    // ---- layer 2 ----
    gemm_k<<<gemm_blocks, 256>>>(h, g2, r2, b2, xgh, rootb2, N);
    pull_k<2><<<pull_blocks, 256>>>(rowptr, edges, (const __half2*)xgh,
                                    (const float2*)rootb2, (float2*)d_out, N);
}